// round 11
// baseline (speedup 1.0000x reference)
#include <cuda_runtime.h>
#include <cuda_fp16.h>
#include <cstdint>

typedef unsigned long long ull;
#define FULLMASK 0xFFFFFFFFu

// Scratch for combined features [vx,vy,vz, rx,ry,rz] per row (64*1024 rows).
__device__ float g_comb[64 * 1024 * 6];

// Prepped W2 (B = W2[k][n]) as mma.sync m16n8k16 B-fragment images, fp16 hi/lo.
// Layout: [nh(2)][kchunk(4)] blocks of 16KB; within block:
// ((kkc*16 + nfh)*32 + lane) * 8 bytes = {b0,b1} u32 pair.
__device__ __align__(16) unsigned char g_bhi[2 * 4 * 16384];
__device__ __align__(16) unsigned char g_blo[2 * 4 * 16384];

// ---------------------------------------------------------------------------
// Kernel 0: prep W2 -> fp16 hi/lo B-fragment images (runs once per launch).
// ---------------------------------------------------------------------------
__device__ __forceinline__ uint32_t pkh2(float lo, float hi) {
    uint32_t r;
    asm("cvt.rn.f16x2.f32 %0, %1, %2;" : "=r"(r) : "f"(hi), "f"(lo));
    return r;
}
__device__ __forceinline__ void splitf(float x, float &hi, float &lo) {
    __half h = __float2half_rn(x);
    hi = __half2float(h);
    lo = x - hi;
}

__global__ void __launch_bounds__(256) w2prep_kernel(const float* __restrict__ W2) {
    const int gid = blockIdx.x * 256 + threadIdx.x;   // 0..16383
    const int lane = gid & 31;
    const int nf = (gid >> 5) & 31;
    const int kk = gid >> 10;                          // 0..15
    const int k0 = kk * 16 + (lane & 3) * 2;
    const int n  = nf * 8 + (lane >> 2);
    float w00 = W2[(k0 + 0) * 256 + n];
    float w01 = W2[(k0 + 1) * 256 + n];
    float w10 = W2[(k0 + 8) * 256 + n];
    float w11 = W2[(k0 + 9) * 256 + n];
    float h00, l00, h01, l01, h10, l10, h11, l11;
    splitf(w00, h00, l00); splitf(w01, h01, l01);
    splitf(w10, h10, l10); splitf(w11, h11, l11);
    const int nh = nf >> 4, c = kk >> 2, kkc = kk & 3, nfh = nf & 15;
    const size_t off = (size_t)(nh * 4 + c) * 16384
                     + (size_t)(((kkc * 16 + nfh) * 32 + lane) * 8);
    *(uint2*)(g_bhi + off) = make_uint2(pkh2(h00, h01), pkh2(h10, h11));
    *(uint2*)(g_blo + off) = make_uint2(pkh2(l00, l01), pkh2(l10, l11));
}

// ---------------------------------------------------------------------------
// Kernel 1: top-4 smallest distances per row -> combined features.
// Warp per row. Each lane issues all 8 LDG.128 for its 32 row-elements UP
// FRONT (4KB independent loads per warp, no smem, no syncs -> deep MLP),
// then scans with a cheap fp32 "min-of-4 <= 4th-best" prefilter guarding the
// exact u64 insert. Final warp butterfly merges per-lane top-4 lists.
// Keys: ((u32)float_bits << 32) | index == exact (value asc, index asc).
// ---------------------------------------------------------------------------

__device__ __forceinline__ void cswap_u64(ull &a, ull &b) {
    if (b < a) { ull t = a; a = b; b = t; }
}

__global__ void __launch_bounds__(256) topk_kernel(
    const float* __restrict__ dm, const float* __restrict__ vel)
{
    const int warp = threadIdx.x >> 5;
    const int lane = threadIdx.x & 31;
    const int row  = blockIdx.x * 8 + warp;          // < 65536
    const float* dl = dm + (size_t)row * 1024 + lane * 4;

    // all 8 loads issued before any consumption (independent LDG.128s)
    float4 v[8];
    #pragma unroll
    for (int g = 0; g < 8; g++)
        v[g] = *(const float4*)(dl + g * 128);

    const ull INIT = ((ull)0x7F800000u << 32) | 0xFFFFFFFFull;  // (+inf,maxidx)
    ull k0 = INIT, k1 = INIT, k2 = INIT, k3 = INIT;
    float t3f = __int_as_float(0x7F800000);

    #pragma unroll
    for (int g = 0; g < 8; g++) {
        float mn = fminf(fminf(v[g].x, v[g].y), fminf(v[g].z, v[g].w));
        if (mn <= t3f) {
            const int jb = g * 128 + lane * 4;
            float e[4] = {v[g].x, v[g].y, v[g].z, v[g].w};
            #pragma unroll
            for (int c = 0; c < 4; c++) {
                if (e[c] <= t3f) {
                    ull key = ((ull)__float_as_uint(e[c]) << 32) | (unsigned)(jb + c);
                    if (key < k3) {
                        k3 = key;
                        cswap_u64(k2, k3);
                        cswap_u64(k1, k2);
                        cswap_u64(k0, k1);
                        t3f = __uint_as_float((unsigned)(k3 >> 32));
                    }
                }
            }
        }
    }

    // warp butterfly merge of per-lane sorted top-4 lists
    #pragma unroll
    for (int off = 16; off; off >>= 1) {
        ull m0 = __shfl_xor_sync(FULLMASK, k0, off);
        ull m1 = __shfl_xor_sync(FULLMASK, k1, off);
        ull m2 = __shfl_xor_sync(FULLMASK, k2, off);
        ull m3 = __shfl_xor_sync(FULLMASK, k3, off);
        if (m0 < k3) {
            #pragma unroll
            for (int i = 0; i < 4; i++) {
                ull m = (i == 0) ? m0 : (i == 1) ? m1 : (i == 2) ? m2 : m3;
                if (m < k3) {
                    k3 = m;
                    cswap_u64(k2, k3);
                    cswap_u64(k1, k2);
                    cswap_u64(k0, k1);
                }
            }
        }
    }

    if (lane == 0) {
        const int b = row >> 10;
        const int a = row & 1023;
        const float* vb = vel + (size_t)b * (1024 * 3);
        const int i1 = (int)(unsigned)k1;
        const int i2 = (int)(unsigned)k2;
        const int i3 = (int)(unsigned)k3;
        float sx = vb[a * 3 + 0], sy = vb[a * 3 + 1], sz = vb[a * 3 + 2];
        float nx = vb[i1 * 3 + 0] + vb[i2 * 3 + 0] + vb[i3 * 3 + 0];
        float ny = vb[i1 * 3 + 1] + vb[i2 * 3 + 1] + vb[i3 * 3 + 1];
        float nz = vb[i1 * 3 + 2] + vb[i2 * 3 + 2] + vb[i3 * 3 + 2];
        const float third = 1.0f / 3.0f;
        float* c = g_comb + (size_t)row * 6;
        c[0] = sx; c[1] = sy; c[2] = sz;
        c[3] = sx - nx * third;
        c[4] = sy - ny * third;
        c[5] = sz - nz * third;
    }
}

// ---------------------------------------------------------------------------
// Kernel 2: fused MLP. GEMM1+ReLU+LN in fp32 (single compute: pre-LN x parked
// as f32 bits in the A smem slots, LN applied in place), then GEMM2 on tensor
// cores via mma.sync m16n8k16 fp16 hi/lo split (3 MMAs, fp32 accumulate).
// Block = 128 rows, 8 warps. N in 2 halves of 128, K in 4 chunks of 64.
// ---------------------------------------------------------------------------

#define AS_U32 132                 // A smem row stride in u32 (conflict-free)
#define A_BYTES (128 * AS_U32 * 4) // 67584 per matrix

#define OFF_W1   0                 // 6144
#define OFF_B1   6144              // 1024
#define OFF_G    7168              // 1024
#define OFF_BT   8192              // 1024
#define OFF_B2   9216              // 1024
#define OFF_CMB  10240             // 3072
#define OFF_AHI  13312             // 67584
#define OFF_ALO  (OFF_AHI + A_BYTES)            // 80896
#define OFF_BH   (OFF_ALO + A_BYTES)            // 148480, 16384
#define OFF_BL   (OFF_BH + 16384)               // 164864, 16384
#define SMEM_MLP (OFF_BL + 16384)               // 181248

__device__ __forceinline__ void mma_hff(float d[4], const uint32_t a[4],
                                        uint32_t b0, uint32_t b1) {
    asm volatile(
        "mma.sync.aligned.m16n8k16.row.col.f32.f16.f16.f32 "
        "{%0,%1,%2,%3}, {%4,%5,%6,%7}, {%8,%9}, {%0,%1,%2,%3};"
        : "+f"(d[0]), "+f"(d[1]), "+f"(d[2]), "+f"(d[3])
        : "r"(a[0]), "r"(a[1]), "r"(a[2]), "r"(a[3]), "r"(b0), "r"(b1));
}

__global__ void __launch_bounds__(256) mlp_kernel(
    const float* __restrict__ W1, const float* __restrict__ b1,
    const float* __restrict__ gamma, const float* __restrict__ beta,
    const float* __restrict__ b2, float* __restrict__ out)
{
    extern __shared__ char smc[];
    float* smf = (float*)smc;

    const int t = threadIdx.x;
    const int wid = t >> 5;
    const int lane = t & 31;
    const int row0 = blockIdx.x * 128;

    for (int i = t; i < 6 * 256; i += 256) smf[OFF_W1 / 4 + i] = W1[i];
    smf[OFF_B1 / 4 + t] = b1[t];
    smf[OFF_G  / 4 + t] = gamma[t];
    smf[OFF_BT / 4 + t] = beta[t];
    smf[OFF_B2 / 4 + t] = b2[t];
    for (int i = t; i < 128 * 6; i += 256)
        smf[OFF_CMB / 4 + i] = g_comb[(size_t)row0 * 6 + i];
    __syncthreads();

    // ---- Phase A: GEMM1+relu once; park x f32 in A slots; pass 2 = LN+split
    {
        const int r = t >> 1;     // row 0..127
        const int q = t & 1;      // e-half
        const float* cm = smf + OFF_CMB / 4 + r * 6;
        const float c0 = cm[0], c1 = cm[1], c2 = cm[2];
        const float c3 = cm[3], c4 = cm[4], c5 = cm[5];
        const float2* w1v = (const float2*)(smc + OFF_W1);
        const float2* b1v = (const float2*)(smc + OFF_B1);
        uint32_t* ahi = (uint32_t*)(smc + OFF_AHI) + r * AS_U32 + 64 * q;
        uint32_t* alo = (uint32_t*)(smc + OFF_ALO) + r * AS_U32 + 64 * q;

        float sum = 0.f, sq = 0.f;
        #pragma unroll 8
        for (int pe = 0; pe < 64; pe++) {
            const int pidx = 64 * q + pe;
            float2 bp = b1v[pidx];
            float x0 = bp.x, x1 = bp.y;
            float2 w;
            w = w1v[0 * 128 + pidx]; x0 = fmaf(c0, w.x, x0); x1 = fmaf(c0, w.y, x1);
            w = w1v[1 * 128 + pidx]; x0 = fmaf(c1, w.x, x0); x1 = fmaf(c1, w.y, x1);
            w = w1v[2 * 128 + pidx]; x0 = fmaf(c2, w.x, x0); x1 = fmaf(c2, w.y, x1);
            w = w1v[3 * 128 + pidx]; x0 = fmaf(c3, w.x, x0); x1 = fmaf(c3, w.y, x1);
            w = w1v[4 * 128 + pidx]; x0 = fmaf(c4, w.x, x0); x1 = fmaf(c4, w.y, x1);
            w = w1v[5 * 128 + pidx]; x0 = fmaf(c5, w.x, x0); x1 = fmaf(c5, w.y, x1);
            x0 = fmaxf(x0, 0.f);
            x1 = fmaxf(x1, 0.f);
            sum += x0 + x1;
            sq = fmaf(x0, x0, fmaf(x1, x1, sq));
            ahi[pe] = __float_as_uint(x0);     // park pre-LN x as f32 bits
            alo[pe] = __float_as_uint(x1);
        }
        sum += __shfl_xor_sync(FULLMASK, sum, 1);
        sq  += __shfl_xor_sync(FULLMASK, sq, 1);
        const float mu   = sum * (1.f / 256.f);
        const float var  = sq * (1.f / 256.f) - mu * mu;
        const float rstd = rsqrtf(var + 1e-5f);

        const float2* gv2 = (const float2*)(smc + OFF_G);
        const float2* bt2 = (const float2*)(smc + OFF_BT);
        #pragma unroll 8
        for (int pe = 0; pe < 64; pe++) {
            const int pidx = 64 * q + pe;
            float x0 = __uint_as_float(ahi[pe]);
            float x1 = __uint_as_float(alo[pe]);
            float2 gp = gv2[pidx];
            float2 tp = bt2[pidx];
            float y0 = fmaf((x0 - mu) * rstd, gp.x, tp.x);
            float y1 = fmaf((x1 - mu) * rstd, gp.y, tp.y);
            float h0, l0, h1, l1;
            splitf(y0, h0, l0);
            splitf(y1, h1, l1);
            ahi[pe] = pkh2(h0, h1);
            alo[pe] = pkh2(l0, l1);
        }
    }
    __syncthreads();

    // ---- Phase B: out = h @ W2 + b2 on tensor cores (3-MMA fp16 split)
    const uint32_t* Ahi = (const uint32_t*)(smc + OFF_AHI) + wid * 16 * AS_U32;
    const uint32_t* Alo = (const uint32_t*)(smc + OFF_ALO) + wid * 16 * AS_U32;
    const int arow = (lane >> 2);            // 0..7
    const int acol = (lane & 3);             // u32 col within k-step

    #pragma unroll 1
    for (int nh = 0; nh < 2; nh++) {
        float acc[16][4];
        #pragma unroll
        for (int nf = 0; nf < 16; nf++)
            #pragma unroll
            for (int j = 0; j < 4; j++) acc[nf][j] = 0.f;

        #pragma unroll 1
        for (int c = 0; c < 4; c++) {
            __syncthreads();   // previous chunk fully consumed
            {
                const float4* sh = (const float4*)(g_bhi + (size_t)(nh * 4 + c) * 16384);
                const float4* sl = (const float4*)(g_blo + (size_t)(nh * 4 + c) * 16384);
                float4* dh = (float4*)(smc + OFF_BH);
                float4* dl = (float4*)(smc + OFF_BL);
                #pragma unroll
                for (int i = 0; i < 4; i++) {
                    dh[t + 256 * i] = sh[t + 256 * i];
                    dl[t + 256 * i] = sl[t + 256 * i];
                }
            }
            __syncthreads();

            #pragma unroll
            for (int kkc = 0; kkc < 4; kkc++) {
                const int ks = c * 4 + kkc;            // global k-step
                const int kb = ks * 8 + acol;          // u32 col base
                uint32_t ah[4], al[4];
                ah[0] = Ahi[(arow + 0) * AS_U32 + kb + 0];
                ah[1] = Ahi[(arow + 8) * AS_U32 + kb + 0];
                ah[2] = Ahi[(arow + 0) * AS_U32 + kb + 4];
                ah[3] = Ahi[(arow + 8) * AS_U32 + kb + 4];
                al[0] = Alo[(arow + 0) * AS_U32 + kb + 0];
                al[1] = Alo[(arow + 8) * AS_U32 + kb + 0];
                al[2] = Alo[(arow + 0) * AS_U32 + kb + 4];
                al[3] = Alo[(arow + 8) * AS_U32 + kb + 4];
                #pragma unroll
                for (int nf = 0; nf < 16; nf++) {
                    const int boff = ((kkc * 16 + nf) * 32 + lane) * 8;
                    uint2 bh = *(const uint2*)(smc + OFF_BH + boff);
                    uint2 bl = *(const uint2*)(smc + OFF_BL + boff);
                    mma_hff(acc[nf], ah, bh.x, bh.y);
                    mma_hff(acc[nf], ah, bl.x, bl.y);
                    mma_hff(acc[nf], al, bh.x, bh.y);
                }
            }
        }

        // epilogue for this n-half
        const int gr = row0 + wid * 16 + arow;
        float* o0 = out + (size_t)gr * 256;
        float* o1 = o0 + 8 * 256;
        const float* b2s = smf + OFF_B2 / 4;
        #pragma unroll
        for (int nf = 0; nf < 16; nf++) {
            const int col = nh * 128 + nf * 8 + (lane & 3) * 2;
            float bx = b2s[col], by = b2s[col + 1];
            float2 v0 = make_float2(acc[nf][0] + bx, acc[nf][1] + by);
            float2 v1 = make_float2(acc[nf][2] + bx, acc[nf][3] + by);
            *(float2*)(o0 + col) = v0;
            *(float2*)(o1 + col) = v1;
        }
    }
}

// ---------------------------------------------------------------------------

extern "C" void kernel_launch(void* const* d_in, const int* in_sizes, int n_in,
                              void* d_out, int out_size) {
    const float* vel   = (const float*)d_in[0];
    const float* dm    = (const float*)d_in[1];
    const float* W1    = (const float*)d_in[2];
    const float* b1    = (const float*)d_in[3];
    const float* gamma = (const float*)d_in[4];
    const float* beta  = (const float*)d_in[5];
    const float* W2    = (const float*)d_in[6];
    const float* b2    = (const float*)d_in[7];
    float* out = (float*)d_out;

    w2prep_kernel<<<64, 256>>>(W2);
    topk_kernel<<<8192, 256>>>(dm, vel);

    cudaFuncSetAttribute(mlp_kernel, cudaFuncAttributeMaxDynamicSharedMemorySize,
                         SMEM_MLP);
    mlp_kernel<<<512, 256, SMEM_MLP>>>(W1, b1, gamma, beta, b2, out);
}

// round 12
// speedup vs baseline: 1.1648x; 1.1648x over previous
#include <cuda_runtime.h>
#include <cuda_fp16.h>
#include <cstdint>

typedef unsigned long long ull;
#define FULLMASK 0xFFFFFFFFu

// Scratch for combined features [vx,vy,vz, rx,ry,rz] per row (64*1024 rows).
__device__ float g_comb[64 * 1024 * 6];

// Prepped W2 (B = W2[k][n]) as mma.sync m16n8k16 B-fragment images, fp16 hi/lo.
// Layout: [nh(2)][kchunk(4)] blocks of 16KB; within block:
// ((kkc*16 + nfh)*32 + lane) * 8 bytes = {b0,b1} u32 pair.
__device__ __align__(16) unsigned char g_bhi[2 * 4 * 16384];
__device__ __align__(16) unsigned char g_blo[2 * 4 * 16384];

// ---------------------------------------------------------------------------
// Kernel 0: prep W2 -> fp16 hi/lo B-fragment images (runs once per launch).
// ---------------------------------------------------------------------------
__device__ __forceinline__ uint32_t pkh2(float lo, float hi) {
    uint32_t r;
    asm("cvt.rn.f16x2.f32 %0, %1, %2;" : "=r"(r) : "f"(hi), "f"(lo));
    return r;
}
__device__ __forceinline__ void splitf(float x, float &hi, float &lo) {
    __half h = __float2half_rn(x);
    hi = __half2float(h);
    lo = x - hi;
}

__global__ void __launch_bounds__(256) w2prep_kernel(const float* __restrict__ W2) {
    const int gid = blockIdx.x * 256 + threadIdx.x;   // 0..16383
    const int lane = gid & 31;
    const int nf = (gid >> 5) & 31;
    const int kk = gid >> 10;                          // 0..15
    const int k0 = kk * 16 + (lane & 3) * 2;
    const int n  = nf * 8 + (lane >> 2);
    float w00 = W2[(k0 + 0) * 256 + n];
    float w01 = W2[(k0 + 1) * 256 + n];
    float w10 = W2[(k0 + 8) * 256 + n];
    float w11 = W2[(k0 + 9) * 256 + n];
    float h00, l00, h01, l01, h10, l10, h11, l11;
    splitf(w00, h00, l00); splitf(w01, h01, l01);
    splitf(w10, h10, l10); splitf(w11, h11, l11);
    const int nh = nf >> 4, c = kk >> 2, kkc = kk & 3, nfh = nf & 15;
    const size_t off = (size_t)(nh * 4 + c) * 16384
                     + (size_t)(((kkc * 16 + nfh) * 32 + lane) * 8);
    *(uint2*)(g_bhi + off) = make_uint2(pkh2(h00, h01), pkh2(h10, h11));
    *(uint2*)(g_blo + off) = make_uint2(pkh2(l00, l01), pkh2(l10, l11));
}

// ---------------------------------------------------------------------------
// Kernel 1: top-4 smallest distances per row -> combined features.
// (R10 staged-smem variant restored — measured best; lane-per-row via
// swizzled 32x128 tiles, fp32 prefilter guarding exact u64 insert)
// ---------------------------------------------------------------------------

__device__ __forceinline__ void cswap_u64(ull &a, ull &b) {
    if (b < a) { ull t = a; a = b; b = t; }
}

#define TK_WARPS 2

__global__ void __launch_bounds__(TK_WARPS * 32) topk_kernel(
    const float* __restrict__ dm, const float* __restrict__ vel)
{
    __shared__ float4 tile[TK_WARPS][32][32];

    const int warp = threadIdx.x >> 5;
    const int lane = threadIdx.x & 31;
    const int row0 = (blockIdx.x * TK_WARPS + warp) * 32;
    const int myrow = row0 + lane;
    const float* base = dm + (size_t)row0 * 1024;

    const ull INIT = ((ull)0x7F800000u << 32) | 0xFFFFFFFFull;
    ull k0 = INIT, k1 = INIT, k2 = INIT, k3 = INIT;
    float t3f = __int_as_float(0x7F800000);

    #pragma unroll 1
    for (int t = 0; t < 8; t++) {
        #pragma unroll
        for (int r = 0; r < 32; r++) {
            float4 v = *(const float4*)(base + (size_t)r * 1024 + t * 128 + lane * 4);
            tile[warp][r][lane ^ r] = v;
        }
        __syncwarp();

        #pragma unroll 4
        for (int g = 0; g < 32; g++) {
            float4 v = tile[warp][lane][g ^ lane];
            float mn = fminf(fminf(v.x, v.y), fminf(v.z, v.w));
            if (mn <= t3f) {
                const int jb = t * 128 + g * 4;
                float e[4] = {v.x, v.y, v.z, v.w};
                #pragma unroll
                for (int c = 0; c < 4; c++) {
                    if (e[c] <= t3f) {
                        ull key = ((ull)__float_as_uint(e[c]) << 32) | (unsigned)(jb + c);
                        if (key < k3) {
                            k3 = key;
                            cswap_u64(k2, k3);
                            cswap_u64(k1, k2);
                            cswap_u64(k0, k1);
                            t3f = __uint_as_float((unsigned)(k3 >> 32));
                        }
                    }
                }
            }
        }
        __syncwarp();
    }

    {
        const int b = myrow >> 10;
        const int a = myrow & 1023;
        const float* vb = vel + (size_t)b * (1024 * 3);
        const int i1 = (int)(unsigned)k1;
        const int i2 = (int)(unsigned)k2;
        const int i3 = (int)(unsigned)k3;
        float sx = vb[a * 3 + 0], sy = vb[a * 3 + 1], sz = vb[a * 3 + 2];
        float nx = vb[i1 * 3 + 0] + vb[i2 * 3 + 0] + vb[i3 * 3 + 0];
        float ny = vb[i1 * 3 + 1] + vb[i2 * 3 + 1] + vb[i3 * 3 + 1];
        float nz = vb[i1 * 3 + 2] + vb[i2 * 3 + 2] + vb[i3 * 3 + 2];
        const float third = 1.0f / 3.0f;
        float* c = g_comb + (size_t)myrow * 6;
        c[0] = sx; c[1] = sy; c[2] = sz;
        c[3] = sx - nx * third;
        c[4] = sy - ny * third;
        c[5] = sz - nz * third;
    }
}

// ---------------------------------------------------------------------------
// Kernel 2: fused MLP, now 512 threads / 16 warps per block (128 rows).
// Phase A: GEMM1+ReLU in fp32 (4 threads/row, x parked in registers), LN,
// split to fp16 hi/lo in smem. Phase B: tensor-core GEMM2 via mma.sync
// m16n8k16 hi/lo split (3 MMAs, fp32 acc); warp wid&7 -> 16-row M tile,
// warp wid>>3 -> N-half (both halves in flight => 4 warps/SMSP latency hiding).
// ---------------------------------------------------------------------------

#define AS_U32 132                 // A smem row stride in u32 (conflict-free)
#define A_BYTES (128 * AS_U32 * 4) // 67584 per matrix

#define OFF_W1   0                 // 6144
#define OFF_B1   6144              // 1024
#define OFF_G    7168              // 1024
#define OFF_BT   8192              // 1024
#define OFF_B2   9216              // 1024
#define OFF_CMB  10240             // 3072 -> ends 13312
#define OFF_AHI  13312             // 67584
#define OFF_ALO  (OFF_AHI + A_BYTES)            // 80896
#define OFF_B    (OFF_ALO + A_BYTES)            // 148480: 4 x 16KB images
#define SMEM_MLP (OFF_B + 65536)                // 214016

__device__ __forceinline__ void mma_hff(float d[4], const uint32_t a[4],
                                        uint32_t b0, uint32_t b1) {
    asm volatile(
        "mma.sync.aligned.m16n8k16.row.col.f32.f16.f16.f32 "
        "{%0,%1,%2,%3}, {%4,%5,%6,%7}, {%8,%9}, {%0,%1,%2,%3};"
        : "+f"(d[0]), "+f"(d[1]), "+f"(d[2]), "+f"(d[3])
        : "r"(a[0]), "r"(a[1]), "r"(a[2]), "r"(a[3]), "r"(b0), "r"(b1));
}

__global__ void __launch_bounds__(512) mlp_kernel(
    const float* __restrict__ W1, const float* __restrict__ b1,
    const float* __restrict__ gamma, const float* __restrict__ beta,
    const float* __restrict__ b2, float* __restrict__ out)
{
    extern __shared__ char smc[];
    float* smf = (float*)smc;

    const int t = threadIdx.x;
    const int wid = t >> 5;
    const int lane = t & 31;
    const int row0 = blockIdx.x * 128;

    for (int i = t; i < 6 * 256; i += 512) smf[OFF_W1 / 4 + i] = W1[i];
    if (t < 256) {
        smf[OFF_B1 / 4 + t] = b1[t];
        smf[OFF_G  / 4 + t] = gamma[t];
        smf[OFF_BT / 4 + t] = beta[t];
        smf[OFF_B2 / 4 + t] = b2[t];
    }
    for (int i = t; i < 128 * 6; i += 512)
        smf[OFF_CMB / 4 + i] = g_comb[(size_t)row0 * 6 + i];
    __syncthreads();

    // ---- Phase A: GEMM1+relu once (x in regs), LN, fp16 hi/lo -> smem.
    // 4 threads/row; thread q handles pair-indices pidx = 4*pe + q so the
    // final STS banks (4r'+q) form a perfect 32-permutation (conflict-free).
    {
        const int r = t >> 2;     // row 0..127
        const int q = t & 3;
        const float* cm = smf + OFF_CMB / 4 + r * 6;
        const float c0 = cm[0], c1 = cm[1], c2 = cm[2];
        const float c3 = cm[3], c4 = cm[4], c5 = cm[5];
        const float2* w1v = (const float2*)(smc + OFF_W1);
        const float2* b1v = (const float2*)(smc + OFF_B1);

        float xs0[32], xs1[32];
        float sum = 0.f, sq = 0.f;
        #pragma unroll
        for (int pe = 0; pe < 32; pe++) {
            const int pidx = 4 * pe + q;
            float2 bp = b1v[pidx];
            float x0 = bp.x, x1 = bp.y;
            float2 w;
            w = w1v[0 * 128 + pidx]; x0 = fmaf(c0, w.x, x0); x1 = fmaf(c0, w.y, x1);
            w = w1v[1 * 128 + pidx]; x0 = fmaf(c1, w.x, x0); x1 = fmaf(c1, w.y, x1);
            w = w1v[2 * 128 + pidx]; x0 = fmaf(c2, w.x, x0); x1 = fmaf(c2, w.y, x1);
            w = w1v[3 * 128 + pidx]; x0 = fmaf(c3, w.x, x0); x1 = fmaf(c3, w.y, x1);
            w = w1v[4 * 128 + pidx]; x0 = fmaf(c4, w.x, x0); x1 = fmaf(c4, w.y, x1);
            w = w1v[5 * 128 + pidx]; x0 = fmaf(c5, w.x, x0); x1 = fmaf(c5, w.y, x1);
            x0 = fmaxf(x0, 0.f);
            x1 = fmaxf(x1, 0.f);
            sum += x0 + x1;
            sq = fmaf(x0, x0, fmaf(x1, x1, sq));
            xs0[pe] = x0;
            xs1[pe] = x1;
        }
        sum += __shfl_xor_sync(FULLMASK, sum, 1);
        sq  += __shfl_xor_sync(FULLMASK, sq, 1);
        sum += __shfl_xor_sync(FULLMASK, sum, 2);
        sq  += __shfl_xor_sync(FULLMASK, sq, 2);
        const float mu   = sum * (1.f / 256.f);
        const float var  = sq * (1.f / 256.f) - mu * mu;
        const float rstd = rsqrtf(var + 1e-5f);

        const float2* gv2 = (const float2*)(smc + OFF_G);
        const float2* bt2 = (const float2*)(smc + OFF_BT);
        uint32_t* ahi = (uint32_t*)(smc + OFF_AHI) + r * AS_U32;
        uint32_t* alo = (uint32_t*)(smc + OFF_ALO) + r * AS_U32;
        #pragma unroll
        for (int pe = 0; pe < 32; pe++) {
            const int pidx = 4 * pe + q;
            float2 gp = gv2[pidx];
            float2 tp = bt2[pidx];
            float y0 = fmaf((xs0[pe] - mu) * rstd, gp.x, tp.x);
            float y1 = fmaf((xs1[pe] - mu) * rstd, gp.y, tp.y);
            float h0, l0, h1, l1;
            splitf(y0, h0, l0);
            splitf(y1, h1, l1);
            ahi[pidx] = pkh2(h0, h1);
            alo[pidx] = pkh2(l0, l1);
        }
    }

    // ---- Phase B: out = h @ W2 + b2 on tensor cores (3-MMA fp16 split)
    const int wp = wid & 7;                  // M tile (rows 16wp..16wp+15)
    const int nh = wid >> 3;                 // N half
    const uint32_t* Ahi = (const uint32_t*)(smc + OFF_AHI) + wp * 16 * AS_U32;
    const uint32_t* Alo = (const uint32_t*)(smc + OFF_ALO) + wp * 16 * AS_U32;
    const int arow = (lane >> 2);            // 0..7
    const int acol = (lane & 3);             // u32 col within k-step
    const char* Bh = smc + OFF_B + nh * 32768;
    const char* Bl = Bh + 16384;

    float acc[16][4];
    #pragma unroll
    for (int nf = 0; nf < 16; nf++)
        #pragma unroll
        for (int j = 0; j < 4; j++) acc[nf][j] = 0.f;

    #pragma unroll 1
    for (int c = 0; c < 4; c++) {
        __syncthreads();   // phase A done / previous chunk fully consumed
        {
            // stage all 4 images for this k-chunk: [nh0 hi][nh0 lo][nh1 hi][nh1 lo]
            const float4* s0 = (const float4*)(g_bhi + (size_t)c * 16384);
            const float4* s1 = (const float4*)(g_blo + (size_t)c * 16384);
            const float4* s2 = (const float4*)(g_bhi + (size_t)(4 + c) * 16384);
            const float4* s3 = (const float4*)(g_blo + (size_t)(4 + c) * 16384);
            float4* d0 = (float4*)(smc + OFF_B);
            float4* d1 = (float4*)(smc + OFF_B + 16384);
            float4* d2 = (float4*)(smc + OFF_B + 32768);
            float4* d3 = (float4*)(smc + OFF_B + 49152);
            #pragma unroll
            for (int i = 0; i < 2; i++) {
                d0[t + 512 * i] = s0[t + 512 * i];
                d1[t + 512 * i] = s1[t + 512 * i];
                d2[t + 512 * i] = s2[t + 512 * i];
                d3[t + 512 * i] = s3[t + 512 * i];
            }
        }
        __syncthreads();

        #pragma unroll
        for (int kkc = 0; kkc < 4; kkc++) {
            const int ks = c * 4 + kkc;            // global k-step
            const int kb = ks * 8 + acol;          // u32 col base
            uint32_t ah[4], al[4];
            ah[0] = Ahi[(arow + 0) * AS_U32 + kb + 0];
            ah[1] = Ahi[(arow + 8) * AS_U32 + kb + 0];
            ah[2] = Ahi[(arow + 0) * AS_U32 + kb + 4];
            ah[3] = Ahi[(arow + 8) * AS_U32 + kb + 4];
            al[0] = Alo[(arow + 0) * AS_U32 + kb + 0];
            al[1] = Alo[(arow + 8) * AS_U32 + kb + 0];
            al[2] = Alo[(arow + 0) * AS_U32 + kb + 4];
            al[3] = Alo[(arow + 8) * AS_U32 + kb + 4];
            #pragma unroll
            for (int nf = 0; nf < 16; nf++) {
                const int boff = ((kkc * 16 + nf) * 32 + lane) * 8;
                uint2 bh = *(const uint2*)(Bh + boff);
                uint2 bl = *(const uint2*)(Bl + boff);
                mma_hff(acc[nf], ah, bh.x, bh.y);
                mma_hff(acc[nf], ah, bl.x, bl.y);
                mma_hff(acc[nf], al, bh.x, bh.y);
            }
        }
    }

    // ---- Epilogue
    {
        const int gr = row0 + wp * 16 + arow;
        float* o0 = out + (size_t)gr * 256;
        float* o1 = o0 + 8 * 256;
        const float* b2s = smf + OFF_B2 / 4;
        #pragma unroll
        for (int nf = 0; nf < 16; nf++) {
            const int col = nh * 128 + nf * 8 + (lane & 3) * 2;
            float bx = b2s[col], by = b2s[col + 1];
            float2 v0 = make_float2(acc[nf][0] + bx, acc[nf][1] + by);
            float2 v1 = make_float2(acc[nf][2] + bx, acc[nf][3] + by);
            *(float2*)(o0 + col) = v0;
            *(float2*)(o1 + col) = v1;
        }
    }
}

// ---------------------------------------------------------------------------

extern "C" void kernel_launch(void* const* d_in, const int* in_sizes, int n_in,
                              void* d_out, int out_size) {
    const float* vel   = (const float*)d_in[0];
    const float* dm    = (const float*)d_in[1];
    const float* W1    = (const float*)d_in[2];
    const float* b1    = (const float*)d_in[3];
    const float* gamma = (const float*)d_in[4];
    const float* beta  = (const float*)d_in[5];
    const float* W2    = (const float*)d_in[6];
    const float* b2    = (const float*)d_in[7];
    float* out = (float*)d_out;

    w2prep_kernel<<<64, 256>>>(W2);
    topk_kernel<<<65536 / (32 * TK_WARPS), TK_WARPS * 32>>>(dm, vel);

    cudaFuncSetAttribute(mlp_kernel, cudaFuncAttributeMaxDynamicSharedMemorySize,
                         SMEM_MLP);
    mlp_kernel<<<512, 512, SMEM_MLP>>>(W1, b1, gamma, beta, b2, out);
}

// round 13
// speedup vs baseline: 1.3199x; 1.1332x over previous
#include <cuda_runtime.h>
#include <cuda_fp16.h>
#include <cstdint>

typedef unsigned long long ull;
#define FULLMASK 0xFFFFFFFFu

// Scratch for combined features [vx,vy,vz, rx,ry,rz] per row (64*1024 rows).
__device__ float g_comb[64 * 1024 * 6];

// Prepped W2 (B = W2[k][n]) as mma.sync m16n8k16 B-fragment images, fp16 hi/lo.
__device__ __align__(16) unsigned char g_bhi[2 * 4 * 16384];
__device__ __align__(16) unsigned char g_blo[2 * 4 * 16384];

// ---------------------------------------------------------------------------
// Kernel 0: prep W2 -> fp16 hi/lo B-fragment images (runs once per launch).
// ---------------------------------------------------------------------------
__device__ __forceinline__ uint32_t pkh2(float lo, float hi) {
    uint32_t r;
    asm("cvt.rn.f16x2.f32 %0, %1, %2;" : "=r"(r) : "f"(hi), "f"(lo));
    return r;
}
__device__ __forceinline__ void splitf(float x, float &hi, float &lo) {
    __half h = __float2half_rn(x);
    hi = __half2float(h);
    lo = x - hi;
}

__global__ void __launch_bounds__(256) w2prep_kernel(const float* __restrict__ W2) {
    const int gid = blockIdx.x * 256 + threadIdx.x;   // 0..16383
    const int lane = gid & 31;
    const int nf = (gid >> 5) & 31;
    const int kk = gid >> 10;                          // 0..15
    const int k0 = kk * 16 + (lane & 3) * 2;
    const int n  = nf * 8 + (lane >> 2);
    float w00 = W2[(k0 + 0) * 256 + n];
    float w01 = W2[(k0 + 1) * 256 + n];
    float w10 = W2[(k0 + 8) * 256 + n];
    float w11 = W2[(k0 + 9) * 256 + n];
    float h00, l00, h01, l01, h10, l10, h11, l11;
    splitf(w00, h00, l00); splitf(w01, h01, l01);
    splitf(w10, h10, l10); splitf(w11, h11, l11);
    const int nh = nf >> 4, c = kk >> 2, kkc = kk & 3, nfh = nf & 15;
    const size_t off = (size_t)(nh * 4 + c) * 16384
                     + (size_t)(((kkc * 16 + nfh) * 32 + lane) * 8);
    *(uint2*)(g_bhi + off) = make_uint2(pkh2(h00, h01), pkh2(h10, h11));
    *(uint2*)(g_blo + off) = make_uint2(pkh2(l00, l01), pkh2(l10, l11));
}

// ---------------------------------------------------------------------------
// Kernel 1: top-4 smallest distances per row -> combined features.
// Lane-per-row, cp.async DOUBLE-BUFFERED 32x64 tiles: loads of tile t+1 are
// in flight while tile t is scanned, so DRAM latency is exposed once per row
// instead of once per tile. fp32 "min-of-4 <= 4th-best" prefilter guards the
// exact u64 insert. Keys ((u32)bits<<32)|idx == exact JAX tie-breaking.
// ---------------------------------------------------------------------------

__device__ __forceinline__ void cswap_u64(ull &a, ull &b) {
    if (b < a) { ull t = a; a = b; b = t; }
}

#define TKW 2          // warps per block
#define TK_TILES 16    // 1024 cols / 64

__global__ void __launch_bounds__(TKW * 32) topk_kernel(
    const float* __restrict__ dm, const float* __restrict__ vel)
{
    // per warp: 2 stages x 32 rows x 17 float4 (pad) = 17408 B
    __shared__ float4 tile[TKW][2][32 * 17];

    const int warp = threadIdx.x >> 5;
    const int lane = threadIdx.x & 31;
    const int row0 = (blockIdx.x * TKW + warp) * 32;
    const int myrow = row0 + lane;
    const float* base = dm + (size_t)row0 * 1024;

    // this lane's fixed staging slot: row pair offset + chunk
    const int sr = lane >> 4;       // 0/1: which row of each pair
    const int sc = lane & 15;       // chunk 0..15

    // prefetch helper (16 cp.async.cg of 16B per lane per tile)
    const ull INIT = ((ull)0x7F800000u << 32) | 0xFFFFFFFFull;
    ull k0 = INIT, k1 = INIT, k2 = INIT, k3 = INIT;
    float t3f = __int_as_float(0x7F800000);

    // issue tile 0
    {
        uint32_t dst0 = (uint32_t)__cvta_generic_to_shared(&tile[warp][0][0]);
        #pragma unroll
        for (int i = 0; i < 16; i++) {
            const int r = 2 * i + sr;
            const float* src = base + (size_t)r * 1024 + sc * 4;
            uint32_t d = dst0 + (uint32_t)(r * 17 + sc) * 16u;
            asm volatile("cp.async.cg.shared.global [%0], [%1], 16;"
                         :: "r"(d), "l"(src) : "memory");
        }
        asm volatile("cp.async.commit_group;" ::: "memory");
    }

    #pragma unroll 1
    for (int t = 0; t < TK_TILES; t++) {
        const int st = t & 1;
        if (t < TK_TILES - 1) {
            uint32_t dstn = (uint32_t)__cvta_generic_to_shared(&tile[warp][st ^ 1][0]);
            #pragma unroll
            for (int i = 0; i < 16; i++) {
                const int r = 2 * i + sr;
                const float* src = base + (size_t)r * 1024 + (t + 1) * 64 + sc * 4;
                uint32_t d = dstn + (uint32_t)(r * 17 + sc) * 16u;
                asm volatile("cp.async.cg.shared.global [%0], [%1], 16;"
                             :: "r"(d), "l"(src) : "memory");
            }
            asm volatile("cp.async.commit_group;" ::: "memory");
            asm volatile("cp.async.wait_group 1;" ::: "memory");
        } else {
            asm volatile("cp.async.wait_group 0;" ::: "memory");
        }
        __syncwarp();

        // scan own row (row index = lane) in tile t
        const float4* myr = &tile[warp][st][lane * 17];
        #pragma unroll 4
        for (int c = 0; c < 16; c++) {
            float4 v = myr[c];
            float mn = fminf(fminf(v.x, v.y), fminf(v.z, v.w));
            if (mn <= t3f) {
                const int jb = t * 64 + c * 4;
                float e[4] = {v.x, v.y, v.z, v.w};
                #pragma unroll
                for (int q = 0; q < 4; q++) {
                    if (e[q] <= t3f) {
                        ull key = ((ull)__float_as_uint(e[q]) << 32) | (unsigned)(jb + q);
                        if (key < k3) {
                            k3 = key;
                            cswap_u64(k2, k3);
                            cswap_u64(k1, k2);
                            cswap_u64(k0, k1);
                            t3f = __uint_as_float((unsigned)(k3 >> 32));
                        }
                    }
                }
            }
        }
        __syncwarp();
    }

    {
        const int b = myrow >> 10;
        const int a = myrow & 1023;
        const float* vb = vel + (size_t)b * (1024 * 3);
        const int i1 = (int)(unsigned)k1;
        const int i2 = (int)(unsigned)k2;
        const int i3 = (int)(unsigned)k3;
        float sx = vb[a * 3 + 0], sy = vb[a * 3 + 1], sz = vb[a * 3 + 2];
        float nx = vb[i1 * 3 + 0] + vb[i2 * 3 + 0] + vb[i3 * 3 + 0];
        float ny = vb[i1 * 3 + 1] + vb[i2 * 3 + 1] + vb[i3 * 3 + 1];
        float nz = vb[i1 * 3 + 2] + vb[i2 * 3 + 2] + vb[i3 * 3 + 2];
        const float third = 1.0f / 3.0f;
        float* c = g_comb + (size_t)myrow * 6;
        c[0] = sx; c[1] = sy; c[2] = sz;
        c[3] = sx - nx * third;
        c[4] = sy - ny * third;
        c[5] = sz - nz * third;
    }
}

// ---------------------------------------------------------------------------
// Kernel noop: shifts the ncu capture window (-s 5 -c 1, 4 launches/call)
// so launch #6 == topk_kernel. Negligible cost (~1-2us).
// ---------------------------------------------------------------------------
__global__ void noop_kernel() {}

// ---------------------------------------------------------------------------
// Kernel 2: fused MLP (unchanged from R12 — 512 thr / 16 warps / 128 rows).
// ---------------------------------------------------------------------------

#define AS_U32 132
#define A_BYTES (128 * AS_U32 * 4)

#define OFF_W1   0
#define OFF_B1   6144
#define OFF_G    7168
#define OFF_BT   8192
#define OFF_B2   9216
#define OFF_CMB  10240
#define OFF_AHI  13312
#define OFF_ALO  (OFF_AHI + A_BYTES)
#define OFF_B    (OFF_ALO + A_BYTES)
#define SMEM_MLP (OFF_B + 65536)

__device__ __forceinline__ void mma_hff(float d[4], const uint32_t a[4],
                                        uint32_t b0, uint32_t b1) {
    asm volatile(
        "mma.sync.aligned.m16n8k16.row.col.f32.f16.f16.f32 "
        "{%0,%1,%2,%3}, {%4,%5,%6,%7}, {%8,%9}, {%0,%1,%2,%3};"
        : "+f"(d[0]), "+f"(d[1]), "+f"(d[2]), "+f"(d[3])
        : "r"(a[0]), "r"(a[1]), "r"(a[2]), "r"(a[3]), "r"(b0), "r"(b1));
}

__global__ void __launch_bounds__(512) mlp_kernel(
    const float* __restrict__ W1, const float* __restrict__ b1,
    const float* __restrict__ gamma, const float* __restrict__ beta,
    const float* __restrict__ b2, float* __restrict__ out)
{
    extern __shared__ char smc[];
    float* smf = (float*)smc;

    const int t = threadIdx.x;
    const int wid = t >> 5;
    const int lane = t & 31;
    const int row0 = blockIdx.x * 128;

    for (int i = t; i < 6 * 256; i += 512) smf[OFF_W1 / 4 + i] = W1[i];
    if (t < 256) {
        smf[OFF_B1 / 4 + t] = b1[t];
        smf[OFF_G  / 4 + t] = gamma[t];
        smf[OFF_BT / 4 + t] = beta[t];
        smf[OFF_B2 / 4 + t] = b2[t];
    }
    for (int i = t; i < 128 * 6; i += 512)
        smf[OFF_CMB / 4 + i] = g_comb[(size_t)row0 * 6 + i];
    __syncthreads();

    // ---- Phase A
    {
        const int r = t >> 2;
        const int q = t & 3;
        const float* cm = smf + OFF_CMB / 4 + r * 6;
        const float c0 = cm[0], c1 = cm[1], c2 = cm[2];
        const float c3 = cm[3], c4 = cm[4], c5 = cm[5];
        const float2* w1v = (const float2*)(smc + OFF_W1);
        const float2* b1v = (const float2*)(smc + OFF_B1);

        float xs0[32], xs1[32];
        float sum = 0.f, sq = 0.f;
        #pragma unroll
        for (int pe = 0; pe < 32; pe++) {
            const int pidx = 4 * pe + q;
            float2 bp = b1v[pidx];
            float x0 = bp.x, x1 = bp.y;
            float2 w;
            w = w1v[0 * 128 + pidx]; x0 = fmaf(c0, w.x, x0); x1 = fmaf(c0, w.y, x1);
            w = w1v[1 * 128 + pidx]; x0 = fmaf(c1, w.x, x0); x1 = fmaf(c1, w.y, x1);
            w = w1v[2 * 128 + pidx]; x0 = fmaf(c2, w.x, x0); x1 = fmaf(c2, w.y, x1);
            w = w1v[3 * 128 + pidx]; x0 = fmaf(c3, w.x, x0); x1 = fmaf(c3, w.y, x1);
            w = w1v[4 * 128 + pidx]; x0 = fmaf(c4, w.x, x0); x1 = fmaf(c4, w.y, x1);
            w = w1v[5 * 128 + pidx]; x0 = fmaf(c5, w.x, x0); x1 = fmaf(c5, w.y, x1);
            x0 = fmaxf(x0, 0.f);
            x1 = fmaxf(x1, 0.f);
            sum += x0 + x1;
            sq = fmaf(x0, x0, fmaf(x1, x1, sq));
            xs0[pe] = x0;
            xs1[pe] = x1;
        }
        sum += __shfl_xor_sync(FULLMASK, sum, 1);
        sq  += __shfl_xor_sync(FULLMASK, sq, 1);
        sum += __shfl_xor_sync(FULLMASK, sum, 2);
        sq  += __shfl_xor_sync(FULLMASK, sq, 2);
        const float mu   = sum * (1.f / 256.f);
        const float var  = sq * (1.f / 256.f) - mu * mu;
        const float rstd = rsqrtf(var + 1e-5f);

        const float2* gv2 = (const float2*)(smc + OFF_G);
        const float2* bt2 = (const float2*)(smc + OFF_BT);
        uint32_t* ahi = (uint32_t*)(smc + OFF_AHI) + r * AS_U32;
        uint32_t* alo = (uint32_t*)(smc + OFF_ALO) + r * AS_U32;
        #pragma unroll
        for (int pe = 0; pe < 32; pe++) {
            const int pidx = 4 * pe + q;
            float2 gp = gv2[pidx];
            float2 tp = bt2[pidx];
            float y0 = fmaf((xs0[pe] - mu) * rstd, gp.x, tp.x);
            float y1 = fmaf((xs1[pe] - mu) * rstd, gp.y, tp.y);
            float h0, l0, h1, l1;
            splitf(y0, h0, l0);
            splitf(y1, h1, l1);
            ahi[pidx] = pkh2(h0, h1);
            alo[pidx] = pkh2(l0, l1);
        }
    }

    // ---- Phase B
    const int wp = wid & 7;
    const int nh = wid >> 3;
    const uint32_t* Ahi = (const uint32_t*)(smc + OFF_AHI) + wp * 16 * AS_U32;
    const uint32_t* Alo = (const uint32_t*)(smc + OFF_ALO) + wp * 16 * AS_U32;
    const int arow = (lane >> 2);
    const int acol = (lane & 3);
    const char* Bh = smc + OFF_B + nh * 32768;
    const char* Bl = Bh + 16384;

    float acc[16][4];
    #pragma unroll
    for (int nf = 0; nf < 16; nf++)
        #pragma unroll
        for (int j = 0; j < 4; j++) acc[nf][j] = 0.f;

    #pragma unroll 1
    for (int c = 0; c < 4; c++) {
        __syncthreads();
        {
            const float4* s0 = (const float4*)(g_bhi + (size_t)c * 16384);
            const float4* s1 = (const float4*)(g_blo + (size_t)c * 16384);
            const float4* s2 = (const float4*)(g_bhi + (size_t)(4 + c) * 16384);
            const float4* s3 = (const float4*)(g_blo + (size_t)(4 + c) * 16384);
            float4* d0 = (float4*)(smc + OFF_B);
            float4* d1 = (float4*)(smc + OFF_B + 16384);
            float4* d2 = (float4*)(smc + OFF_B + 32768);
            float4* d3 = (float4*)(smc + OFF_B + 49152);
            #pragma unroll
            for (int i = 0; i < 2; i++) {
                d0[t + 512 * i] = s0[t + 512 * i];
                d1[t + 512 * i] = s1[t + 512 * i];
                d2[t + 512 * i] = s2[t + 512 * i];
                d3[t + 512 * i] = s3[t + 512 * i];
            }
        }
        __syncthreads();

        #pragma unroll
        for (int kkc = 0; kkc < 4; kkc++) {
            const int ks = c * 4 + kkc;
            const int kb = ks * 8 + acol;
            uint32_t ah[4], al[4];
            ah[0] = Ahi[(arow + 0) * AS_U32 + kb + 0];
            ah[1] = Ahi[(arow + 8) * AS_U32 + kb + 0];
            ah[2] = Ahi[(arow + 0) * AS_U32 + kb + 4];
            ah[3] = Ahi[(arow + 8) * AS_U32 + kb + 4];
            al[0] = Alo[(arow + 0) * AS_U32 + kb + 0];
            al[1] = Alo[(arow + 8) * AS_U32 + kb + 0];
            al[2] = Alo[(arow + 0) * AS_U32 + kb + 4];
            al[3] = Alo[(arow + 8) * AS_U32 + kb + 4];
            #pragma unroll
            for (int nf = 0; nf < 16; nf++) {
                const int boff = ((kkc * 16 + nf) * 32 + lane) * 8;
                uint2 bh = *(const uint2*)(Bh + boff);
                uint2 bl = *(const uint2*)(Bl + boff);
                mma_hff(acc[nf], ah, bh.x, bh.y);
                mma_hff(acc[nf], ah, bl.x, bl.y);
                mma_hff(acc[nf], al, bh.x, bh.y);
            }
        }
    }

    // ---- Epilogue
    {
        const int gr = row0 + wp * 16 + arow;
        float* o0 = out + (size_t)gr * 256;
        float* o1 = o0 + 8 * 256;
        const float* b2s = smf + OFF_B2 / 4;
        #pragma unroll
        for (int nf = 0; nf < 16; nf++) {
            const int col = nh * 128 + nf * 8 + (lane & 3) * 2;
            float bx = b2s[col], by = b2s[col + 1];
            float2 v0 = make_float2(acc[nf][0] + bx, acc[nf][1] + by);
            float2 v1 = make_float2(acc[nf][2] + bx, acc[nf][3] + by);
            *(float2*)(o0 + col) = v0;
            *(float2*)(o1 + col) = v1;
        }
    }
}

// ---------------------------------------------------------------------------

extern "C" void kernel_launch(void* const* d_in, const int* in_sizes, int n_in,
                              void* d_out, int out_size) {
    const float* vel   = (const float*)d_in[0];
    const float* dm    = (const float*)d_in[1];
    const float* W1    = (const float*)d_in[2];
    const float* b1    = (const float*)d_in[3];
    const float* gamma = (const float*)d_in[4];
    const float* beta  = (const float*)d_in[5];
    const float* W2    = (const float*)d_in[6];
    const float* b2    = (const float*)d_in[7];
    float* out = (float*)d_out;

    // 4 launches/call so ncu (-s 5 -c 1) lands on topk_kernel (launch #6).
    w2prep_kernel<<<64, 256>>>(W2);
    topk_kernel<<<65536 / (32 * TKW), TKW * 32>>>(dm, vel);

    cudaFuncSetAttribute(mlp_kernel, cudaFuncAttributeMaxDynamicSharedMemorySize,
                         SMEM_MLP);
    mlp_kernel<<<512, 512, SMEM_MLP>>>(W1, b1, gamma, beta, b2, out);

    noop_kernel<<<1, 32>>>();
}

// round 14
// speedup vs baseline: 1.4553x; 1.1026x over previous
#include <cuda_runtime.h>
#include <cuda_fp16.h>
#include <cstdint>

typedef unsigned long long ull;
#define FULLMASK 0xFFFFFFFFu

// Scratch for combined features [vx,vy,vz, rx,ry,rz] per row (64*1024 rows).
__device__ float g_comb[64 * 1024 * 6];

// Prepped W2 (B = W2[k][n]) as mma.sync m16n8k16 B-fragment images, fp16 hi/lo.
__device__ __align__(16) unsigned char g_bhi[2 * 4 * 16384];
__device__ __align__(16) unsigned char g_blo[2 * 4 * 16384];

// ---------------------------------------------------------------------------
// Kernel 0: prep W2 -> fp16 hi/lo B-fragment images (runs once per launch).
// ---------------------------------------------------------------------------
__device__ __forceinline__ uint32_t pkh2(float lo, float hi) {
    uint32_t r;
    asm("cvt.rn.f16x2.f32 %0, %1, %2;" : "=r"(r) : "f"(hi), "f"(lo));
    return r;
}
__device__ __forceinline__ void splitf(float x, float &hi, float &lo) {
    __half h = __float2half_rn(x);
    hi = __half2float(h);
    lo = x - hi;
}

__global__ void __launch_bounds__(256) w2prep_kernel(const float* __restrict__ W2) {
    const int gid = blockIdx.x * 256 + threadIdx.x;   // 0..16383
    const int lane = gid & 31;
    const int nf = (gid >> 5) & 31;
    const int kk = gid >> 10;                          // 0..15
    const int k0 = kk * 16 + (lane & 3) * 2;
    const int n  = nf * 8 + (lane >> 2);
    float w00 = W2[(k0 + 0) * 256 + n];
    float w01 = W2[(k0 + 1) * 256 + n];
    float w10 = W2[(k0 + 8) * 256 + n];
    float w11 = W2[(k0 + 9) * 256 + n];
    float h00, l00, h01, l01, h10, l10, h11, l11;
    splitf(w00, h00, l00); splitf(w01, h01, l01);
    splitf(w10, h10, l10); splitf(w11, h11, l11);
    const int nh = nf >> 4, c = kk >> 2, kkc = kk & 3, nfh = nf & 15;
    const size_t off = (size_t)(nh * 4 + c) * 16384
                     + (size_t)(((kkc * 16 + nfh) * 32 + lane) * 8);
    *(uint2*)(g_bhi + off) = make_uint2(pkh2(h00, h01), pkh2(h10, h11));
    *(uint2*)(g_blo + off) = make_uint2(pkh2(l00, l01), pkh2(l10, l11));
}

// ---------------------------------------------------------------------------
// Kernel 1: top-4 smallest distances per row -> combined features.
// Lane-per-row, cp.async 4-STAGE pipeline on 32x32 tiles (prefetch distance 3
// covers DRAM latency; 2-stage only covered one scan-time). fp32 prefilter
// guards the exact u64 insert. Keys ((u32)bits<<32)|idx == JAX tie-breaking.
// ---------------------------------------------------------------------------

__device__ __forceinline__ void cswap_u64(ull &a, ull &b) {
    if (b < a) { ull t = a; a = b; b = t; }
}

#define TKW 2           // warps per block
#define TK_ST 4         // pipeline stages
#define TK_TILES 32     // 1024 cols / 32

__global__ void __launch_bounds__(TKW * 32) topk_kernel(
    const float* __restrict__ dm, const float* __restrict__ vel)
{
    // per warp: 4 stages x 32 rows x 9 float4 (stride-9 pad) = 18432 B
    __shared__ float4 tile[TKW][TK_ST][32 * 9];

    const int warp = threadIdx.x >> 5;
    const int lane = threadIdx.x & 31;
    const int row0 = (blockIdx.x * TKW + warp) * 32;
    const int myrow = row0 + lane;
    const float* base = dm + (size_t)row0 * 1024;

    const ull INIT = ((ull)0x7F800000u << 32) | 0xFFFFFFFFull;
    ull k0 = INIT, k1 = INIT, k2 = INIT, k3 = INIT;
    float t3f = __int_as_float(0x7F800000);

    // lane -> 8 fixed 16B chunks per tile: chunk = lane + 32*i,
    // row = chunk/8, col = chunk%8 (each 128B row segment fully coalesced)
    uint32_t sbase = (uint32_t)__cvta_generic_to_shared(&tile[warp][0][0]);

    // preissue tiles 0..2
    #pragma unroll
    for (int p = 0; p < TK_ST - 1; p++) {
        uint32_t dst = sbase + (uint32_t)p * (32 * 9 * 16);
        #pragma unroll
        for (int i = 0; i < 8; i++) {
            const int ch = lane + 32 * i;
            const int r = ch >> 3, cc = ch & 7;
            const float* src = base + (size_t)r * 1024 + p * 32 + cc * 4;
            asm volatile("cp.async.cg.shared.global [%0], [%1], 16;"
                         :: "r"(dst + (uint32_t)(r * 9 + cc) * 16u), "l"(src)
                         : "memory");
        }
        asm volatile("cp.async.commit_group;" ::: "memory");
    }

    #pragma unroll 1
    for (int t = 0; t < TK_TILES; t++) {
        if (t + 3 < TK_TILES) {
            const int p = t + 3;
            uint32_t dst = sbase + (uint32_t)(p & (TK_ST - 1)) * (32 * 9 * 16);
            #pragma unroll
            for (int i = 0; i < 8; i++) {
                const int ch = lane + 32 * i;
                const int r = ch >> 3, cc = ch & 7;
                const float* src = base + (size_t)r * 1024 + p * 32 + cc * 4;
                asm volatile("cp.async.cg.shared.global [%0], [%1], 16;"
                             :: "r"(dst + (uint32_t)(r * 9 + cc) * 16u), "l"(src)
                             : "memory");
            }
            asm volatile("cp.async.commit_group;" ::: "memory");
            asm volatile("cp.async.wait_group 3;" ::: "memory");
        } else if (t + 3 == TK_TILES) {
            asm volatile("cp.async.wait_group 2;" ::: "memory");
        } else if (t + 2 == TK_TILES) {
            asm volatile("cp.async.wait_group 1;" ::: "memory");
        } else {
            asm volatile("cp.async.wait_group 0;" ::: "memory");
        }
        __syncwarp();

        // scan own row (row index = lane) in tile t
        const float4* myr = &tile[warp][t & (TK_ST - 1)][lane * 9];
        #pragma unroll
        for (int c = 0; c < 8; c++) {
            float4 v = myr[c];
            float mn = fminf(fminf(v.x, v.y), fminf(v.z, v.w));
            if (mn <= t3f) {
                const int jb = t * 32 + c * 4;
                float e[4] = {v.x, v.y, v.z, v.w};
                #pragma unroll
                for (int q = 0; q < 4; q++) {
                    if (e[q] <= t3f) {
                        ull key = ((ull)__float_as_uint(e[q]) << 32) | (unsigned)(jb + q);
                        if (key < k3) {
                            k3 = key;
                            cswap_u64(k2, k3);
                            cswap_u64(k1, k2);
                            cswap_u64(k0, k1);
                            t3f = __uint_as_float((unsigned)(k3 >> 32));
                        }
                    }
                }
            }
        }
        __syncwarp();   // all lanes done scanning before buffer reuse
    }

    {
        const int b = myrow >> 10;
        const int a = myrow & 1023;
        const float* vb = vel + (size_t)b * (1024 * 3);
        const int i1 = (int)(unsigned)k1;
        const int i2 = (int)(unsigned)k2;
        const int i3 = (int)(unsigned)k3;
        float sx = vb[a * 3 + 0], sy = vb[a * 3 + 1], sz = vb[a * 3 + 2];
        float nx = vb[i1 * 3 + 0] + vb[i2 * 3 + 0] + vb[i3 * 3 + 0];
        float ny = vb[i1 * 3 + 1] + vb[i2 * 3 + 1] + vb[i3 * 3 + 1];
        float nz = vb[i1 * 3 + 2] + vb[i2 * 3 + 2] + vb[i3 * 3 + 2];
        const float third = 1.0f / 3.0f;
        float* c = g_comb + (size_t)myrow * 6;
        c[0] = sx; c[1] = sy; c[2] = sz;
        c[3] = sx - nx * third;
        c[4] = sy - ny * third;
        c[5] = sz - nz * third;
    }
}

// ---------------------------------------------------------------------------
// Kernel 2: fused MLP. GEMM1+ReLU+LN in fp32; GEMM2 on tensor cores with
// 2-MMA fp16 split: A = rn16(h) (hi only), B = hi+lo -> D = ah*bh + ah*bl.
// Dropped al*bh term contributes ~1.4e-4 rel err (vs 1e-3 threshold).
// 512 threads / 16 warps / 128 rows; warp wid&7 -> M tile, wid>>3 -> N half.
// ---------------------------------------------------------------------------

#define AS_U32 132
#define A_BYTES (128 * AS_U32 * 4)

#define OFF_W1   0
#define OFF_B1   6144
#define OFF_G    7168
#define OFF_BT   8192
#define OFF_B2   9216
#define OFF_CMB  10240
#define OFF_AHI  13312
#define OFF_B    (OFF_AHI + A_BYTES)     // 80896: 4 x 16KB B images
#define SMEM_MLP (OFF_B + 65536)         // 146432

__device__ __forceinline__ void mma_hff(float d[4], const uint32_t a[4],
                                        uint32_t b0, uint32_t b1) {
    asm volatile(
        "mma.sync.aligned.m16n8k16.row.col.f32.f16.f16.f32 "
        "{%0,%1,%2,%3}, {%4,%5,%6,%7}, {%8,%9}, {%0,%1,%2,%3};"
        : "+f"(d[0]), "+f"(d[1]), "+f"(d[2]), "+f"(d[3])
        : "r"(a[0]), "r"(a[1]), "r"(a[2]), "r"(a[3]), "r"(b0), "r"(b1));
}

__global__ void __launch_bounds__(512) mlp_kernel(
    const float* __restrict__ W1, const float* __restrict__ b1,
    const float* __restrict__ gamma, const float* __restrict__ beta,
    const float* __restrict__ b2, float* __restrict__ out)
{
    extern __shared__ char smc[];
    float* smf = (float*)smc;

    const int t = threadIdx.x;
    const int wid = t >> 5;
    const int lane = t & 31;
    const int row0 = blockIdx.x * 128;

    for (int i = t; i < 6 * 256; i += 512) smf[OFF_W1 / 4 + i] = W1[i];
    if (t < 256) {
        smf[OFF_B1 / 4 + t] = b1[t];
        smf[OFF_G  / 4 + t] = gamma[t];
        smf[OFF_BT / 4 + t] = beta[t];
        smf[OFF_B2 / 4 + t] = b2[t];
    }
    for (int i = t; i < 128 * 6; i += 512)
        smf[OFF_CMB / 4 + i] = g_comb[(size_t)row0 * 6 + i];
    __syncthreads();

    // ---- Phase A: GEMM1+relu (x in regs), LN, fp16 -> smem (hi only)
    {
        const int r = t >> 2;
        const int q = t & 3;
        const float* cm = smf + OFF_CMB / 4 + r * 6;
        const float c0 = cm[0], c1 = cm[1], c2 = cm[2];
        const float c3 = cm[3], c4 = cm[4], c5 = cm[5];
        const float2* w1v = (const float2*)(smc + OFF_W1);
        const float2* b1v = (const float2*)(smc + OFF_B1);

        float xs0[32], xs1[32];
        float sum = 0.f, sq = 0.f;
        #pragma unroll
        for (int pe = 0; pe < 32; pe++) {
            const int pidx = 4 * pe + q;
            float2 bp = b1v[pidx];
            float x0 = bp.x, x1 = bp.y;
            float2 w;
            w = w1v[0 * 128 + pidx]; x0 = fmaf(c0, w.x, x0); x1 = fmaf(c0, w.y, x1);
            w = w1v[1 * 128 + pidx]; x0 = fmaf(c1, w.x, x0); x1 = fmaf(c1, w.y, x1);
            w = w1v[2 * 128 + pidx]; x0 = fmaf(c2, w.x, x0); x1 = fmaf(c2, w.y, x1);
            w = w1v[3 * 128 + pidx]; x0 = fmaf(c3, w.x, x0); x1 = fmaf(c3, w.y, x1);
            w = w1v[4 * 128 + pidx]; x0 = fmaf(c4, w.x, x0); x1 = fmaf(c4, w.y, x1);
            w = w1v[5 * 128 + pidx]; x0 = fmaf(c5, w.x, x0); x1 = fmaf(c5, w.y, x1);
            x0 = fmaxf(x0, 0.f);
            x1 = fmaxf(x1, 0.f);
            sum += x0 + x1;
            sq = fmaf(x0, x0, fmaf(x1, x1, sq));
            xs0[pe] = x0;
            xs1[pe] = x1;
        }
        sum += __shfl_xor_sync(FULLMASK, sum, 1);
        sq  += __shfl_xor_sync(FULLMASK, sq, 1);
        sum += __shfl_xor_sync(FULLMASK, sum, 2);
        sq  += __shfl_xor_sync(FULLMASK, sq, 2);
        const float mu   = sum * (1.f / 256.f);
        const float var  = sq * (1.f / 256.f) - mu * mu;
        const float rstd = rsqrtf(var + 1e-5f);

        const float2* gv2 = (const float2*)(smc + OFF_G);
        const float2* bt2 = (const float2*)(smc + OFF_BT);
        uint32_t* ahi = (uint32_t*)(smc + OFF_AHI) + r * AS_U32;
        #pragma unroll
        for (int pe = 0; pe < 32; pe++) {
            const int pidx = 4 * pe + q;
            float2 gp = gv2[pidx];
            float2 tp = bt2[pidx];
            float y0 = fmaf((xs0[pe] - mu) * rstd, gp.x, tp.x);
            float y1 = fmaf((xs1[pe] - mu) * rstd, gp.y, tp.y);
            ahi[pidx] = pkh2(y0, y1);   // rn16 of y, packed
        }
    }

    // ---- Phase B: out = h @ W2 + b2 (2 MMAs: ah*bh + ah*bl)
    const int wp = wid & 7;
    const int nh = wid >> 3;
    const uint32_t* Ahi = (const uint32_t*)(smc + OFF_AHI) + wp * 16 * AS_U32;
    const int arow = (lane >> 2);
    const int acol = (lane & 3);
    const char* Bh = smc + OFF_B + nh * 32768;
    const char* Bl = Bh + 16384;

    float acc[16][4];
    #pragma unroll
    for (int nf = 0; nf < 16; nf++)
        #pragma unroll
        for (int j = 0; j < 4; j++) acc[nf][j] = 0.f;

    #pragma unroll 1
    for (int c = 0; c < 4; c++) {
        __syncthreads();
        {
            const float4* s0 = (const float4*)(g_bhi + (size_t)c * 16384);
            const float4* s1 = (const float4*)(g_blo + (size_t)c * 16384);
            const float4* s2 = (const float4*)(g_bhi + (size_t)(4 + c) * 16384);
            const float4* s3 = (const float4*)(g_blo + (size_t)(4 + c) * 16384);
            float4* d0 = (float4*)(smc + OFF_B);
            float4* d1 = (float4*)(smc + OFF_B + 16384);
            float4* d2 = (float4*)(smc + OFF_B + 32768);
            float4* d3 = (float4*)(smc + OFF_B + 49152);
            #pragma unroll
            for (int i = 0; i < 2; i++) {
                d0[t + 512 * i] = s0[t + 512 * i];
                d1[t + 512 * i] = s1[t + 512 * i];
                d2[t + 512 * i] = s2[t + 512 * i];
                d3[t + 512 * i] = s3[t + 512 * i];
            }
        }
        __syncthreads();

        #pragma unroll
        for (int kkc = 0; kkc < 4; kkc++) {
            const int ks = c * 4 + kkc;
            const int kb = ks * 8 + acol;
            uint32_t ah[4];
            ah[0] = Ahi[(arow + 0) * AS_U32 + kb + 0];
            ah[1] = Ahi[(arow + 8) * AS_U32 + kb + 0];
            ah[2] = Ahi[(arow + 0) * AS_U32 + kb + 4];
            ah[3] = Ahi[(arow + 8) * AS_U32 + kb + 4];
            #pragma unroll
            for (int nf = 0; nf < 16; nf++) {
                const int boff = ((kkc * 16 + nf) * 32 + lane) * 8;
                uint2 bh = *(const uint2*)(Bh + boff);
                uint2 bl = *(const uint2*)(Bl + boff);
                mma_hff(acc[nf], ah, bh.x, bh.y);
                mma_hff(acc[nf], ah, bl.x, bl.y);
            }
        }
    }

    // ---- Epilogue
    {
        const int gr = row0 + wp * 16 + arow;
        float* o0 = out + (size_t)gr * 256;
        float* o1 = o0 + 8 * 256;
        const float* b2s = smf + OFF_B2 / 4;
        #pragma unroll
        for (int nf = 0; nf < 16; nf++) {
            const int col = nh * 128 + nf * 8 + (lane & 3) * 2;
            float bx = b2s[col], by = b2s[col + 1];
            float2 v0 = make_float2(acc[nf][0] + bx, acc[nf][1] + by);
            float2 v1 = make_float2(acc[nf][2] + bx, acc[nf][3] + by);
            *(float2*)(o0 + col) = v0;
            *(float2*)(o1 + col) = v1;
        }
    }
}

// ---------------------------------------------------------------------------

extern "C" void kernel_launch(void* const* d_in, const int* in_sizes, int n_in,
                              void* d_out, int out_size) {
    const float* vel   = (const float*)d_in[0];
    const float* dm    = (const float*)d_in[1];
    const float* W1    = (const float*)d_in[2];
    const float* b1    = (const float*)d_in[3];
    const float* gamma = (const float*)d_in[4];
    const float* beta  = (const float*)d_in[5];
    const float* W2    = (const float*)d_in[6];
    const float* b2    = (const float*)d_in[7];
    float* out = (float*)d_out;

    w2prep_kernel<<<64, 256>>>(W2);
    topk_kernel<<<65536 / (32 * TKW), TKW * 32>>>(dm, vel);

    cudaFuncSetAttribute(mlp_kernel, cudaFuncAttributeMaxDynamicSharedMemorySize,
                         SMEM_MLP);
    mlp_kernel<<<512, 512, SMEM_MLP>>>(W1, b1, gamma, beta, b2, out);
}